// round 1
// baseline (speedup 1.0000x reference)
#include <cuda_runtime.h>
#include <math.h>

#define BB 2
#define NHALF 1024
#define SS 2048
#define DIM 768
#define NH 12
#define HD 64
#define COND 128
#define BLK 16
#define MTOT (BB*SS)          // 4096
#define MODS (6*DIM)          // 4608

// ---------------- scratch (device globals; no allocation allowed) ----------------
__device__ float g_mods[BB*MODS];
__device__ float g_h[MTOT*DIM];
__device__ float g_qkv[(size_t)MTOT*3*DIM];
__device__ float g_a[MTOT*DIM];
__device__ float g_x2[MTOT*DIM];
__device__ float g_mlp[(size_t)MTOT*4*DIM];

// ---------------- adaLN: mods = c @ W^T + b ----------------
__global__ void adaln_k(const float* __restrict__ c, const float* __restrict__ w,
                        const float* __restrict__ b, float* __restrict__ mods) {
    int j = blockIdx.x * blockDim.x + threadIdx.x;
    if (j >= BB * MODS) return;
    int bb = j / MODS;
    int n  = j % MODS;
    const float* cr = c + bb * COND;
    const float* wr = w + (size_t)n * COND;
    float acc = b[n];
#pragma unroll 8
    for (int k = 0; k < COND; k++) acc += cr[k] * wr[k];
    mods[j] = acc;
}

// ---------------- LayerNorm + modulate: out = ln(x)*w*(1+scale)+shift ----------------
__global__ void ln_mod_k(const float* __restrict__ x, const float* __restrict__ w,
                         const float* __restrict__ mods, float* __restrict__ out,
                         int shift_off, int scale_off) {
    int row = blockIdx.x;              // b*S + s
    int bb  = row / SS;
    const float* xr = x + (size_t)row * DIM;
    int tid = threadIdx.x;

    float s = 0.f, s2 = 0.f;
    for (int j = tid; j < DIM; j += blockDim.x) {
        float v = xr[j];
        s += v; s2 += v * v;
    }
#pragma unroll
    for (int o = 16; o; o >>= 1) {
        s  += __shfl_xor_sync(0xffffffffu, s,  o);
        s2 += __shfl_xor_sync(0xffffffffu, s2, o);
    }
    __shared__ float wsum[8], wsum2[8];
    __shared__ float s_mu, s_rv;
    if ((tid & 31) == 0) { wsum[tid >> 5] = s; wsum2[tid >> 5] = s2; }
    __syncthreads();
    if (tid == 0) {
        float t = 0.f, t2 = 0.f;
        for (int i = 0; i < 8; i++) { t += wsum[i]; t2 += wsum2[i]; }
        float mu = t / DIM;
        float var = t2 / DIM - mu * mu;
        s_mu = mu;
        s_rv = rsqrtf(var + 1e-5f);
    }
    __syncthreads();
    float mu = s_mu, rv = s_rv;
    const float* msh = mods + bb * MODS + shift_off;
    const float* msc = mods + bb * MODS + scale_off;
    float* orow = out + (size_t)row * DIM;
    for (int j = tid; j < DIM; j += blockDim.x)
        orow[j] = (xr[j] - mu) * rv * w[j] * (1.f + msc[j]) + msh[j];
}

// ---------------- Tiled GEMM:  C[M,N] = A[M,K] @ Bw[N,K]^T  (+ epilogues) ----------------
// mode 0: none
// mode 1: C = gelu_tanh(acc + bias[n])
// mode 2: C = res[m,n] + mods[b*MODS+gate_off+n] * (acc + (bias?bias[n]:0))
__device__ __forceinline__ float gelu_tanh(float x) {
    float x3 = x * x * x;
    return 0.5f * x * (1.f + tanhf(0.7978845608028654f * (x + 0.044715f * x3)));
}

__global__ __launch_bounds__(256) void gemm_nt_k(
    const float* __restrict__ A, const float* __restrict__ Bw, float* __restrict__ C,
    int M, int Ncols, int K,
    const float* __restrict__ bias, const float* __restrict__ res,
    const float* __restrict__ mods, int gate_off, int mode) {
    __shared__ float As[64][33];
    __shared__ float Bs[64][33];
    int tid = threadIdx.x;
    int tx = tid & 15, ty = tid >> 4;
    int m0 = blockIdx.y * 64, n0 = blockIdx.x * 64;
    float acc[4][4] = {};

    for (int k0 = 0; k0 < K; k0 += 32) {
#pragma unroll
        for (int i = 0; i < 8; i++) {
            int idx = i * 256 + tid;
            int r = idx >> 5, cc = idx & 31;
            As[r][cc] = A[(size_t)(m0 + r) * K + k0 + cc];
            Bs[r][cc] = Bw[(size_t)(n0 + r) * K + k0 + cc];
        }
        __syncthreads();
#pragma unroll
        for (int kk = 0; kk < 32; kk++) {
            float a[4], bv[4];
#pragma unroll
            for (int i = 0; i < 4; i++) a[i] = As[ty * 4 + i][kk];
#pragma unroll
            for (int j = 0; j < 4; j++) bv[j] = Bs[tx * 4 + j][kk];
#pragma unroll
            for (int i = 0; i < 4; i++)
#pragma unroll
                for (int j = 0; j < 4; j++) acc[i][j] += a[i] * bv[j];
        }
        __syncthreads();
    }

#pragma unroll
    for (int i = 0; i < 4; i++) {
        int m = m0 + ty * 4 + i;
        int bb = m / SS;
#pragma unroll
        for (int j = 0; j < 4; j++) {
            int n = n0 + tx * 4 + j;
            float v = acc[i][j];
            if (mode == 1) {
                v = gelu_tanh(v + bias[n]);
            } else if (mode == 2) {
                if (bias) v += bias[n];
                float g = mods[bb * MODS + gate_off + n];
                v = res[(size_t)m * Ncols + n] + g * v;
            }
            C[(size_t)m * Ncols + n] = v;
        }
    }
}

// ---------------- RoPE over all of qkv (reference rotates q, k AND v) ----------------
__global__ void rope_k(float* __restrict__ qkv, const float* __restrict__ cosb,
                       const float* __restrict__ sinb) {
    int i = blockIdx.x * blockDim.x + threadIdx.x;
    int total = MTOT * 3 * NH * (HD / 2);
    if (i >= total) return;
    int d = i & 31;
    int rest = i >> 5;
    int hh = rest % NH; rest /= NH;
    int t  = rest % 3;  rest /= 3;
    int s  = rest % SS;
    int bb = rest / SS;
    size_t base = ((((size_t)bb * SS + s) * 3 + t) * NH + hh) * HD;
    float x1 = qkv[base + d], x2 = qkv[base + d + 32];
    float c1 = cosb[s * HD + d],      sn1 = sinb[s * HD + d];
    float c2 = cosb[s * HD + d + 32], sn2 = sinb[s * HD + d + 32];
    qkv[base + d]      = x1 * c1 - x2 * sn1;
    qkv[base + d + 32] = x2 * c2 + x1 * sn2;
}

// ---------------- Attention: one block per (q, b*H+h). Analytic mask. ----------------
__global__ __launch_bounds__(128) void attn_k(const float* __restrict__ qkv,
                                              float* __restrict__ out) {
    int q  = blockIdx.x;
    int bh = blockIdx.y;
    int bb = bh / NH, hh = bh % NH;
    __shared__ float sc[SS];
    __shared__ float qv[HD];
    __shared__ float red[128];
    int tid = threadIdx.x;

    const float* qptr = qkv + ((((size_t)bb * SS + q) * 3 + 0) * NH + hh) * HD;
    if (tid < HD) qv[tid] = qptr[tid];
    __syncthreads();

    int flq  = (q >= NHALF) ? 1 : 0;
    int blkq = (flq ? (q - NHALF) : q) / BLK;

    float lmax = -1e38f;
    for (int k = tid; k < SS; k += 128) {
        int flk  = (k >= NHALF) ? 1 : 0;
        int blkk = (flk ? (k - NHALF) : k) / BLK;
        bool m = (blkq == blkk && flq == flk) ||
                 (blkq > 0 && blkk < blkq && flk == 1);
        float v;
        if (m) {
            const float* kptr = qkv + ((((size_t)bb * SS + k) * 3 + 1) * NH + hh) * HD;
            float dot = 0.f;
#pragma unroll
            for (int d = 0; d < HD; d++) dot += qv[d] * kptr[d];
            v = dot * 0.125f;
        } else {
            v = -1e30f;
        }
        sc[k] = v;
        lmax = fmaxf(lmax, v);
    }
    red[tid] = lmax;
    __syncthreads();
#pragma unroll
    for (int o = 64; o; o >>= 1) {
        if (tid < o) red[tid] = fmaxf(red[tid], red[tid + o]);
        __syncthreads();
    }
    float mx = red[0];
    __syncthreads();

    float lsum = 0.f;
    for (int k = tid; k < SS; k += 128) {
        float e = __expf(sc[k] - mx);
        sc[k] = e;
        lsum += e;
    }
    red[tid] = lsum;
    __syncthreads();
#pragma unroll
    for (int o = 64; o; o >>= 1) {
        if (tid < o) red[tid] += red[tid + o];
        __syncthreads();
    }
    float inv = 1.f / red[0];
    __syncthreads();

    // pass 2: 2 half-ranges of k per head-dim lane
    int d   = tid & 63;
    int half = tid >> 6;
    int kbeg = half * (SS / 2), kend = kbeg + (SS / 2);
    const float* vp = qkv + ((((size_t)bb * SS + kbeg) * 3 + 2) * NH + hh) * HD + d;
    float a = 0.f;
    for (int k = kbeg; k < kend; k++) {
        float p = sc[k];
        if (p != 0.f) a += p * (*vp);
        vp += 3 * NH * HD;
    }
    red[tid] = a;
    __syncthreads();
    if (tid < 64) {
        float r = (red[tid] + red[tid + 64]) * inv;
        out[((size_t)bb * SS + q) * DIM + hh * HD + tid] = r;
    }
}

// ---------------- launch ----------------
extern "C" void kernel_launch(void* const* d_in, const int* in_sizes, int n_in,
                              void* d_out, int out_size) {
    const float* x        = (const float*)d_in[0];
    const float* c        = (const float*)d_in[1];
    const float* cosb     = (const float*)d_in[2];
    const float* sinb     = (const float*)d_in[3];
    /* d_in[4] = mask (recomputed analytically in-kernel) */
    const float* norm1_w  = (const float*)d_in[5];
    const float* qkv_w    = (const float*)d_in[6];
    const float* attn_w   = (const float*)d_in[7];
    const float* norm2_w  = (const float*)d_in[8];
    const float* mlp_w1   = (const float*)d_in[9];
    const float* mlp_b1   = (const float*)d_in[10];
    const float* mlp_w2   = (const float*)d_in[11];
    const float* mlp_b2   = (const float*)d_in[12];
    const float* adaLN_w  = (const float*)d_in[13];
    const float* adaLN_b  = (const float*)d_in[14];
    float* out = (float*)d_out;

    float *mods, *hbuf, *qkvb, *abuf, *x2, *mlp;
    cudaGetSymbolAddress((void**)&mods, g_mods);
    cudaGetSymbolAddress((void**)&hbuf, g_h);
    cudaGetSymbolAddress((void**)&qkvb, g_qkv);
    cudaGetSymbolAddress((void**)&abuf, g_a);
    cudaGetSymbolAddress((void**)&x2,   g_x2);
    cudaGetSymbolAddress((void**)&mlp,  g_mlp);

    // 1. adaLN modulation vector
    adaln_k<<<(BB * MODS + 255) / 256, 256>>>(c, adaLN_w, adaLN_b, mods);

    // 2. norm1 + modulate (shift_msa @0, scale_msa @DIM)
    ln_mod_k<<<MTOT, 256>>>(x, norm1_w, mods, hbuf, 0, DIM);

    // 3. QKV projection
    gemm_nt_k<<<dim3(3 * DIM / 64, MTOT / 64), 256>>>(
        hbuf, qkv_w, qkvb, MTOT, 3 * DIM, DIM, nullptr, nullptr, nullptr, 0, 0);

    // 4. RoPE on whole qkv
    rope_k<<<(MTOT * 3 * NH * 32 + 255) / 256, 256>>>(qkvb, cosb, sinb);

    // 5. Attention
    attn_k<<<dim3(SS, BB * NH), 128>>>(qkvb, abuf);

    // 6. attn-out projection + gate_msa (@2*DIM) * () + x residual
    gemm_nt_k<<<dim3(DIM / 64, MTOT / 64), 256>>>(
        abuf, attn_w, x2, MTOT, DIM, DIM, nullptr, x, mods, 2 * DIM, 2);

    // 7. norm2 + modulate (shift_mlp @3*DIM, scale_mlp @4*DIM)
    ln_mod_k<<<MTOT, 256>>>(x2, norm2_w, mods, hbuf, 3 * DIM, 4 * DIM);

    // 8. MLP up + gelu
    gemm_nt_k<<<dim3(4 * DIM / 64, MTOT / 64), 256>>>(
        hbuf, mlp_w1, mlp, MTOT, 4 * DIM, DIM, mlp_b1, nullptr, nullptr, 0, 1);

    // 9. MLP down + bias + gate_mlp (@5*DIM) * () + x2 residual -> d_out
    gemm_nt_k<<<dim3(DIM / 64, MTOT / 64), 256>>>(
        mlp, mlp_w2, out, MTOT, DIM, 4 * DIM, mlp_b2, x2, mods, 5 * DIM, 2);
}

// round 2
// speedup vs baseline: 2.8911x; 2.8911x over previous
#include <cuda_runtime.h>
#include <math.h>

#define BB 2
#define NHALF 1024
#define SS 2048
#define DIM 768
#define NH 12
#define HD 64
#define COND 128
#define BLK 16
#define MTOT (BB*SS)          // 4096
#define MODS (6*DIM)          // 4608

// ---------------- scratch (device globals; no allocation allowed) ----------------
__device__ float g_mods[BB*MODS];
__device__ float g_h[MTOT*DIM];
__device__ float g_qkv[(size_t)MTOT*3*DIM];
__device__ float g_a[MTOT*DIM];
__device__ float g_x2[MTOT*DIM];
__device__ float g_mlp[(size_t)MTOT*4*DIM];

// ---------------- adaLN: mods = c @ W^T + b ----------------
__global__ void adaln_k(const float* __restrict__ c, const float* __restrict__ w,
                        const float* __restrict__ b, float* __restrict__ mods) {
    int j = blockIdx.x * blockDim.x + threadIdx.x;
    if (j >= BB * MODS) return;
    int bb = j / MODS;
    int n  = j % MODS;
    const float* cr = c + bb * COND;
    const float* wr = w + (size_t)n * COND;
    float acc = b[n];
#pragma unroll 8
    for (int k = 0; k < COND; k++) acc += cr[k] * wr[k];
    mods[j] = acc;
}

// ---------------- LayerNorm + modulate ----------------
__global__ void ln_mod_k(const float* __restrict__ x, const float* __restrict__ w,
                         const float* __restrict__ mods, float* __restrict__ out,
                         int shift_off, int scale_off) {
    int row = blockIdx.x;
    int bb  = row / SS;
    const float* xr = x + (size_t)row * DIM;
    int tid = threadIdx.x;

    float s = 0.f, s2 = 0.f;
    for (int j = tid; j < DIM; j += blockDim.x) {
        float v = xr[j];
        s += v; s2 += v * v;
    }
#pragma unroll
    for (int o = 16; o; o >>= 1) {
        s  += __shfl_xor_sync(0xffffffffu, s,  o);
        s2 += __shfl_xor_sync(0xffffffffu, s2, o);
    }
    __shared__ float wsum[8], wsum2[8];
    __shared__ float s_mu, s_rv;
    if ((tid & 31) == 0) { wsum[tid >> 5] = s; wsum2[tid >> 5] = s2; }
    __syncthreads();
    if (tid == 0) {
        float t = 0.f, t2 = 0.f;
        for (int i = 0; i < 8; i++) { t += wsum[i]; t2 += wsum2[i]; }
        float mu = t / DIM;
        float var = t2 / DIM - mu * mu;
        s_mu = mu;
        s_rv = rsqrtf(var + 1e-5f);
    }
    __syncthreads();
    float mu = s_mu, rv = s_rv;
    const float* msh = mods + bb * MODS + shift_off;
    const float* msc = mods + bb * MODS + scale_off;
    float* orow = out + (size_t)row * DIM;
    for (int j = tid; j < DIM; j += blockDim.x)
        orow[j] = (xr[j] - mu) * rv * w[j] * (1.f + msc[j]) + msh[j];
}

// ---------------- Tiled GEMM 128x128x32, 8x8 micro (2x4 split) ----------------
// C[M,N] = A[M,K] @ Bw[N,K]^T  + epilogues
// mode 0: none
// mode 1: C = gelu_tanh(acc + bias[n])
// mode 2: C = res[m,n] + mods[b*MODS+gate_off+n] * (acc + (bias?bias[n]:0))
__device__ __forceinline__ float gelu_tanh(float x) {
    float x3 = x * x * x;
    return 0.5f * x * (1.f + tanhf(0.7978845608028654f * (x + 0.044715f * x3)));
}

#define GBM 128
#define GBN 128
#define GBK 32
#define GPAD 132   // 16B-aligned row stride

__global__ __launch_bounds__(256) void gemm128_k(
    const float* __restrict__ A, const float* __restrict__ Bw, float* __restrict__ C,
    int M, int Ncols, int K,
    const float* __restrict__ bias, const float* __restrict__ res,
    const float* __restrict__ mods, int gate_off, int mode) {
    __shared__ float As[GBK][GPAD];   // As[k][m]
    __shared__ float Bs[GBK][GPAD];   // Bs[k][n]
    int tid = threadIdx.x;
    int tx = tid & 15, ty = tid >> 4;
    int m0 = blockIdx.y * GBM, n0 = blockIdx.x * GBN;
    float acc[8][8];
#pragma unroll
    for (int i = 0; i < 8; i++)
#pragma unroll
        for (int j = 0; j < 8; j++) acc[i][j] = 0.f;

    for (int k0 = 0; k0 < K; k0 += GBK) {
#pragma unroll
        for (int i = 0; i < 16; i++) {
            int idx = i * 256 + tid;
            int r = idx >> 5, kk = idx & 31;
            As[kk][r] = A[(size_t)(m0 + r) * K + k0 + kk];
            Bs[kk][r] = Bw[(size_t)(n0 + r) * K + k0 + kk];
        }
        __syncthreads();
#pragma unroll
        for (int kk = 0; kk < GBK; kk++) {
            float4 a0 = *(const float4*)&As[kk][ty * 4];
            float4 a1 = *(const float4*)&As[kk][64 + ty * 4];
            float4 b0 = *(const float4*)&Bs[kk][tx * 4];
            float4 b1 = *(const float4*)&Bs[kk][64 + tx * 4];
            float av[8] = {a0.x, a0.y, a0.z, a0.w, a1.x, a1.y, a1.z, a1.w};
            float bv[8] = {b0.x, b0.y, b0.z, b0.w, b1.x, b1.y, b1.z, b1.w};
#pragma unroll
            for (int i = 0; i < 8; i++)
#pragma unroll
                for (int j = 0; j < 8; j++) acc[i][j] += av[i] * bv[j];
        }
        __syncthreads();
    }

#pragma unroll
    for (int i = 0; i < 8; i++) {
        int m = m0 + (i < 4 ? ty * 4 + i : 64 + ty * 4 + i - 4);
        int bb = m / SS;
#pragma unroll
        for (int j = 0; j < 8; j++) {
            int n = n0 + (j < 4 ? tx * 4 + j : 64 + tx * 4 + j - 4);
            float v = acc[i][j];
            if (mode == 1) {
                v = gelu_tanh(v + bias[n]);
            } else if (mode == 2) {
                if (bias) v += bias[n];
                float g = mods[bb * MODS + gate_off + n];
                v = res[(size_t)m * Ncols + n] + g * v;
            }
            C[(size_t)m * Ncols + n] = v;
        }
    }
}

// ---------------- RoPE over all of qkv (reference rotates q, k AND v) ----------------
__global__ void rope_k(float* __restrict__ qkv, const float* __restrict__ cosb,
                       const float* __restrict__ sinb) {
    int i = blockIdx.x * blockDim.x + threadIdx.x;
    int total = MTOT * 3 * NH * (HD / 2);
    if (i >= total) return;
    int d = i & 31;
    int rest = i >> 5;
    int hh = rest % NH; rest /= NH;
    int t  = rest % 3;  rest /= 3;
    int s  = rest % SS;
    int bb = rest / SS;
    size_t base = ((((size_t)bb * SS + s) * 3 + t) * NH + hh) * HD;
    float x1 = qkv[base + d], x2 = qkv[base + d + 32];
    float c1 = cosb[s * HD + d],      sn1 = sinb[s * HD + d];
    float c2 = cosb[s * HD + d + 32], sn2 = sinb[s * HD + d + 32];
    qkv[base + d]      = x1 * c1 - x2 * sn1;
    qkv[base + d + 32] = x2 * c2 + x1 * sn2;
}

// ---------------- Block-sparse flash attention ----------------
// grid: (128 q-blocks, B*H). All 16 queries of a block share the same mask.
// Allowed keys: own 16-key block + (blkq>0 ? blocks 0..blkq-1 of half-2 : none).
__global__ __launch_bounds__(256) void attn_blk_k(const float* __restrict__ qkv,
                                                  float* __restrict__ out) {
    int qb = blockIdx.x;                 // 0..127
    int bh = blockIdx.y;
    int bb = bh / NH, hh = bh % NH;
    int flq  = (qb >= 64) ? 1 : 0;
    int blkq = flq ? qb - 64 : qb;
    int q0   = (flq ? NHALF : 0) + blkq * BLK;

    __shared__ float qs[BLK][HD + 1];
    __shared__ float ks[BLK][HD + 1];
    __shared__ float vs[BLK][HD];
    __shared__ float sP[BLK][17];
    __shared__ float sm_m[BLK], sm_l[BLK], sm_c[BLK];

    int tid = threadIdx.x;
    // load Q tile
#pragma unroll
    for (int i = 0; i < 4; i++) {
        int idx = i * 256 + tid;
        int r = idx >> 6, d = idx & 63;
        qs[r][d] = qkv[((((size_t)bb * SS + q0 + r) * 3 + 0) * NH + hh) * HD + d];
    }
    if (tid < BLK) { sm_m[tid] = -1e30f; sm_l[tid] = 0.f; }
    __syncthreads();

    float accv[4] = {0.f, 0.f, 0.f, 0.f};
    int qi_s = tid >> 4, ki_s = tid & 15;     // score-phase mapping
    int d_p  = tid & 63, qg = tid >> 6;       // PV-phase mapping

    int nkb = 1 + (blkq > 0 ? blkq : 0);
    for (int t = 0; t < nkb; t++) {
        int ks0 = (t == 0) ? q0 : (NHALF + (t - 1) * BLK);
        // load K and V tiles (coalesced)
#pragma unroll
        for (int i = 0; i < 4; i++) {
            int idx = i * 256 + tid;
            int r = idx >> 6, d = idx & 63;
            size_t base = (((size_t)bb * SS + ks0 + r) * 3) * NH * HD + (size_t)hh * HD + d;
            ks[r][d] = qkv[base + (size_t)1 * NH * HD];
            vs[r][d] = qkv[base + (size_t)2 * NH * HD];
        }
        __syncthreads();

        // scores: one (qi,ki) per thread
        float dot = 0.f;
#pragma unroll
        for (int d = 0; d < HD; d++) dot += qs[qi_s][d] * ks[ki_s][d];
        float s = dot * 0.125f;

        float bm = s;
#pragma unroll
        for (int o = 8; o; o >>= 1) bm = fmaxf(bm, __shfl_xor_sync(0xffffffffu, bm, o, 16));
        float m_old = sm_m[qi_s];
        float m_new = fmaxf(m_old, bm);
        float p = __expf(s - m_new);
        float ps = p;
#pragma unroll
        for (int o = 8; o; o >>= 1) ps += __shfl_xor_sync(0xffffffffu, ps, o, 16);
        sP[qi_s][ki_s] = p;
        if (ki_s == 0) {
            float corr = __expf(m_old - m_new);
            sm_c[qi_s] = corr;
            sm_l[qi_s] = sm_l[qi_s] * corr + ps;
            sm_m[qi_s] = m_new;
        }
        __syncthreads();

        // PV: thread handles 4 (qi,d) outputs
#pragma unroll
        for (int ii = 0; ii < 4; ii++) {
            int qi = qg * 4 + ii;
            float sum = 0.f;
#pragma unroll
            for (int ki = 0; ki < BLK; ki++) sum += sP[qi][ki] * vs[ki][d_p];
            accv[ii] = accv[ii] * sm_c[qi] + sum;
        }
        __syncthreads();
    }

#pragma unroll
    for (int ii = 0; ii < 4; ii++) {
        int qi = qg * 4 + ii;
        float inv = 1.f / sm_l[qi];
        out[((size_t)bb * SS + q0 + qi) * DIM + hh * HD + d_p] = accv[ii] * inv;
    }
}

// ---------------- launch ----------------
extern "C" void kernel_launch(void* const* d_in, const int* in_sizes, int n_in,
                              void* d_out, int out_size) {
    const float* x        = (const float*)d_in[0];
    const float* c        = (const float*)d_in[1];
    const float* cosb     = (const float*)d_in[2];
    const float* sinb     = (const float*)d_in[3];
    /* d_in[4] = mask (recomputed analytically in-kernel) */
    const float* norm1_w  = (const float*)d_in[5];
    const float* qkv_w    = (const float*)d_in[6];
    const float* attn_w   = (const float*)d_in[7];
    const float* norm2_w  = (const float*)d_in[8];
    const float* mlp_w1   = (const float*)d_in[9];
    const float* mlp_b1   = (const float*)d_in[10];
    const float* mlp_w2   = (const float*)d_in[11];
    const float* mlp_b2   = (const float*)d_in[12];
    const float* adaLN_w  = (const float*)d_in[13];
    const float* adaLN_b  = (const float*)d_in[14];
    float* out = (float*)d_out;

    float *mods, *hbuf, *qkvb, *abuf, *x2, *mlp;
    cudaGetSymbolAddress((void**)&mods, g_mods);
    cudaGetSymbolAddress((void**)&hbuf, g_h);
    cudaGetSymbolAddress((void**)&qkvb, g_qkv);
    cudaGetSymbolAddress((void**)&abuf, g_a);
    cudaGetSymbolAddress((void**)&x2,   g_x2);
    cudaGetSymbolAddress((void**)&mlp,  g_mlp);

    // 1. adaLN modulation vector
    adaln_k<<<(BB * MODS + 255) / 256, 256>>>(c, adaLN_w, adaLN_b, mods);

    // 2. norm1 + modulate (shift_msa @0, scale_msa @DIM)
    ln_mod_k<<<MTOT, 256>>>(x, norm1_w, mods, hbuf, 0, DIM);

    // 3. QKV projection
    gemm128_k<<<dim3(3 * DIM / GBN, MTOT / GBM), 256>>>(
        hbuf, qkv_w, qkvb, MTOT, 3 * DIM, DIM, nullptr, nullptr, nullptr, 0, 0);

    // 4. RoPE on whole qkv
    rope_k<<<(MTOT * 3 * NH * 32 + 255) / 256, 256>>>(qkvb, cosb, sinb);

    // 5. Block-sparse flash attention
    attn_blk_k<<<dim3(SS / BLK, BB * NH), 256>>>(qkvb, abuf);

    // 6. attn-out projection + gate_msa (@2*DIM) + x residual
    gemm128_k<<<dim3(DIM / GBN, MTOT / GBM), 256>>>(
        abuf, attn_w, x2, MTOT, DIM, DIM, nullptr, x, mods, 2 * DIM, 2);

    // 7. norm2 + modulate (shift_mlp @3*DIM, scale_mlp @4*DIM)
    ln_mod_k<<<MTOT, 256>>>(x2, norm2_w, mods, hbuf, 3 * DIM, 4 * DIM);

    // 8. MLP up + gelu
    gemm128_k<<<dim3(4 * DIM / GBN, MTOT / GBM), 256>>>(
        hbuf, mlp_w1, mlp, MTOT, 4 * DIM, DIM, mlp_b1, nullptr, nullptr, 0, 1);

    // 9. MLP down + bias + gate_mlp (@5*DIM) + x2 residual -> d_out
    gemm128_k<<<dim3(DIM / GBN, MTOT / GBM), 256>>>(
        mlp, mlp_w2, out, MTOT, DIM, 4 * DIM, mlp_b2, x2, mods, 5 * DIM, 2);
}

// round 4
// speedup vs baseline: 7.4290x; 2.5696x over previous
#include <cuda_runtime.h>
#include <math.h>
#include <stdint.h>

#define BB 2
#define NHALF 1024
#define SS 2048
#define DIM 768
#define NH 12
#define HD 64
#define COND 128
#define BLK 16
#define MTOT (BB*SS)          // 4096
#define MODS (6*DIM)          // 4608

// ---------------- scratch (device globals; no allocation allowed) ----------------
__device__ float g_mods[BB*MODS];
__device__ float g_h[MTOT*DIM];
__device__ float g_qkv[(size_t)MTOT*3*DIM];
__device__ float g_a[MTOT*DIM];
__device__ float g_x2[MTOT*DIM];
__device__ float g_mlp[(size_t)MTOT*4*DIM];

// ---------------- adaLN: mods = c @ W^T + b ----------------
__global__ void adaln_k(const float* __restrict__ c, const float* __restrict__ w,
                        const float* __restrict__ b, float* __restrict__ mods) {
    int j = blockIdx.x * blockDim.x + threadIdx.x;
    if (j >= BB * MODS) return;
    int bb = j / MODS;
    int n  = j % MODS;
    const float* cr = c + bb * COND;
    const float* wr = w + (size_t)n * COND;
    float acc = b[n];
#pragma unroll 8
    for (int k = 0; k < COND; k++) acc += cr[k] * wr[k];
    mods[j] = acc;
}

// ---------------- LayerNorm + modulate ----------------
__global__ void ln_mod_k(const float* __restrict__ x, const float* __restrict__ w,
                         const float* __restrict__ mods, float* __restrict__ out,
                         int shift_off, int scale_off) {
    int row = blockIdx.x;
    int bb  = row / SS;
    const float* xr = x + (size_t)row * DIM;
    int tid = threadIdx.x;

    float s = 0.f, s2 = 0.f;
    for (int j = tid; j < DIM; j += blockDim.x) {
        float v = xr[j];
        s += v; s2 += v * v;
    }
#pragma unroll
    for (int o = 16; o; o >>= 1) {
        s  += __shfl_xor_sync(0xffffffffu, s,  o);
        s2 += __shfl_xor_sync(0xffffffffu, s2, o);
    }
    __shared__ float wsum[8], wsum2[8];
    __shared__ float s_mu, s_rv;
    if ((tid & 31) == 0) { wsum[tid >> 5] = s; wsum2[tid >> 5] = s2; }
    __syncthreads();
    if (tid == 0) {
        float t = 0.f, t2 = 0.f;
        for (int i = 0; i < 8; i++) { t += wsum[i]; t2 += wsum2[i]; }
        float mu = t / DIM;
        float var = t2 / DIM - mu * mu;
        s_mu = mu;
        s_rv = rsqrtf(var + 1e-5f);
    }
    __syncthreads();
    float mu = s_mu, rv = s_rv;
    const float* msh = mods + bb * MODS + shift_off;
    const float* msc = mods + bb * MODS + scale_off;
    float* orow = out + (size_t)row * DIM;
    for (int j = tid; j < DIM; j += blockDim.x)
        orow[j] = (xr[j] - mu) * rv * w[j] * (1.f + msc[j]) + msh[j];
}

// ---------------- tf32 tensor-core GEMM ----------------
// C[M,N] = A[M,K] @ Bw[N,K]^T   (+ epilogues)
// block 128x128, 4 warps (2x2), warp tile 64x64, BK=32, mma m16n8k8 tf32
__device__ __forceinline__ float gelu_tanh(float x) {
    float x3 = x * x * x;
    return 0.5f * x * (1.f + tanhf(0.7978845608028654f * (x + 0.044715f * x3)));
}
__device__ __forceinline__ uint32_t f2tf32(float f) {
    uint32_t u;
    asm("cvt.rna.tf32.f32 %0, %1;" : "=r"(u) : "f"(f));
    return u;
}
__device__ __forceinline__ void mma_tf32(float c[4], const uint32_t a[4], const uint32_t b[2]) {
    asm volatile(
        "mma.sync.aligned.m16n8k8.row.col.f32.tf32.tf32.f32 "
        "{%0,%1,%2,%3},{%4,%5,%6,%7},{%8,%9},{%0,%1,%2,%3};"
        : "+f"(c[0]), "+f"(c[1]), "+f"(c[2]), "+f"(c[3])
        : "r"(a[0]), "r"(a[1]), "r"(a[2]), "r"(a[3]), "r"(b[0]), "r"(b[1]));
}

#define GSTR 36   // smem row stride (u32); 36 % 32 == 4 -> conflict-free frag gather

__global__ __launch_bounds__(128) void gemm_tc_k(
    const float* __restrict__ A, const float* __restrict__ Bw, float* __restrict__ C,
    int M, int Ncols, int K,
    const float* __restrict__ bias, const float* __restrict__ res,
    const float* __restrict__ mods, int gate_off, int mode) {
    __shared__ uint32_t As[128 * GSTR];   // [m][k] tf32 bits
    __shared__ uint32_t Bs[128 * GSTR];   // [n][k] tf32 bits
    int tid  = threadIdx.x;
    int wid  = tid >> 5, lane = tid & 31;
    int wm   = wid >> 1, wn = wid & 1;       // 2x2 warp grid
    int g    = lane >> 2, t = lane & 3;
    int m0   = blockIdx.y * 128, n0 = blockIdx.x * 128;

    float acc[4][8][4];
#pragma unroll
    for (int i = 0; i < 4; i++)
#pragma unroll
        for (int j = 0; j < 8; j++)
#pragma unroll
            for (int r = 0; r < 4; r++) acc[i][j][r] = 0.f;

    for (int k0 = 0; k0 < K; k0 += 32) {
#pragma unroll
        for (int i = 0; i < 8; i++) {
            int e = i * 128 + tid;
            int r = e >> 3, cc = (e & 7) * 4;
            float4 va = *(const float4*)&A [(size_t)(m0 + r) * K + k0 + cc];
            float4 vb = *(const float4*)&Bw[(size_t)(n0 + r) * K + k0 + cc];
            uint32_t* pa = &As[r * GSTR + cc];
            pa[0] = f2tf32(va.x); pa[1] = f2tf32(va.y);
            pa[2] = f2tf32(va.z); pa[3] = f2tf32(va.w);
            uint32_t* pb = &Bs[r * GSTR + cc];
            pb[0] = f2tf32(vb.x); pb[1] = f2tf32(vb.y);
            pb[2] = f2tf32(vb.z); pb[3] = f2tf32(vb.w);
        }
        __syncthreads();
#pragma unroll
        for (int ks = 0; ks < 4; ks++) {
            int kb = ks * 8;
            uint32_t af[4][4], bf[8][2];
#pragma unroll
            for (int mt = 0; mt < 4; mt++) {
                int r = wm * 64 + mt * 16 + g;
                af[mt][0] = As[r * GSTR + kb + t];
                af[mt][1] = As[(r + 8) * GSTR + kb + t];
                af[mt][2] = As[r * GSTR + kb + t + 4];
                af[mt][3] = As[(r + 8) * GSTR + kb + t + 4];
            }
#pragma unroll
            for (int nt = 0; nt < 8; nt++) {
                int rn = wn * 64 + nt * 8 + g;
                bf[nt][0] = Bs[rn * GSTR + kb + t];
                bf[nt][1] = Bs[rn * GSTR + kb + t + 4];
            }
#pragma unroll
            for (int mt = 0; mt < 4; mt++)
#pragma unroll
                for (int nt = 0; nt < 8; nt++) mma_tf32(acc[mt][nt], af[mt], bf[nt]);
        }
        __syncthreads();
    }

    // epilogue
#pragma unroll
    for (int mt = 0; mt < 4; mt++) {
        int r0 = m0 + wm * 64 + mt * 16 + g;
#pragma unroll
        for (int half = 0; half < 2; half++) {
            int m = r0 + half * 8;
            int bb = m / SS;
#pragma unroll
            for (int nt = 0; nt < 8; nt++) {
                int n = n0 + wn * 64 + nt * 8 + 2 * t;
                float v0 = acc[mt][nt][half * 2 + 0];
                float v1 = acc[mt][nt][half * 2 + 1];
                if (mode == 1) {
                    v0 = gelu_tanh(v0 + bias[n]);
                    v1 = gelu_tanh(v1 + bias[n + 1]);
                } else if (mode == 2) {
                    if (bias) { v0 += bias[n]; v1 += bias[n + 1]; }
                    float g0 = mods[bb * MODS + gate_off + n];
                    float g1 = mods[bb * MODS + gate_off + n + 1];
                    v0 = res[(size_t)m * Ncols + n]     + g0 * v0;
                    v1 = res[(size_t)m * Ncols + n + 1] + g1 * v1;
                }
                *(float2*)&C[(size_t)m * Ncols + n] = make_float2(v0, v1);
            }
        }
    }
}

// ---------------- RoPE over all of qkv (reference rotates q, k AND v) ----------------
__global__ void rope_k(float* __restrict__ qkv, const float* __restrict__ cosb,
                       const float* __restrict__ sinb) {
    int i = blockIdx.x * blockDim.x + threadIdx.x;
    int total = MTOT * 3 * NH * (HD / 2);
    if (i >= total) return;
    int d = i & 31;
    int rest = i >> 5;
    int hh = rest % NH; rest /= NH;
    int t  = rest % 3;  rest /= 3;
    int s  = rest % SS;
    int bb = rest / SS;
    size_t base = ((((size_t)bb * SS + s) * 3 + t) * NH + hh) * HD;
    float x1 = qkv[base + d], x2 = qkv[base + d + 32];
    float c1 = cosb[s * HD + d],      sn1 = sinb[s * HD + d];
    float c2 = cosb[s * HD + d + 32], sn2 = sinb[s * HD + d + 32];
    qkv[base + d]      = x1 * c1 - x2 * sn1;
    qkv[base + d + 32] = x2 * c2 + x1 * sn2;
}

// ---------------- Block-sparse flash attention ----------------
#define QPAD 68   // row stride (floats): 272 bytes, 16B-divisible -> aligned LDS.128
__global__ __launch_bounds__(256) void attn_blk_k(const float* __restrict__ qkv,
                                                  float* __restrict__ out) {
    int qb = blockIdx.x;                 // 0..127
    int bh = blockIdx.y;
    int bb = bh / NH, hh = bh % NH;
    int flq  = (qb >= 64) ? 1 : 0;
    int blkq = flq ? qb - 64 : qb;
    int q0   = (flq ? NHALF : 0) + blkq * BLK;

    __shared__ float qs[BLK][QPAD];
    __shared__ float ks[BLK][QPAD];
    __shared__ float vs[BLK][HD];
    __shared__ float sP[BLK][17];
    __shared__ float sm_m[BLK], sm_l[BLK], sm_c[BLK];

    int tid = threadIdx.x;
#pragma unroll
    for (int i = 0; i < 4; i++) {
        int idx = i * 256 + tid;
        int r = idx >> 6, d = idx & 63;
        qs[r][d] = qkv[((((size_t)bb * SS + q0 + r) * 3 + 0) * NH + hh) * HD + d];
    }
    if (tid < BLK) { sm_m[tid] = -1e30f; sm_l[tid] = 0.f; }
    __syncthreads();

    float accv[4] = {0.f, 0.f, 0.f, 0.f};
    int qi_s = tid >> 4, ki_s = tid & 15;
    int d_p  = tid & 63, qg = tid >> 6;

    int nkb = 1 + (blkq > 0 ? blkq : 0);
    for (int t = 0; t < nkb; t++) {
        int ks0 = (t == 0) ? q0 : (NHALF + (t - 1) * BLK);
#pragma unroll
        for (int i = 0; i < 4; i++) {
            int idx = i * 256 + tid;
            int r = idx >> 6, d = idx & 63;
            size_t base = (((size_t)bb * SS + ks0 + r) * 3) * NH * HD + (size_t)hh * HD + d;
            ks[r][d] = qkv[base + (size_t)1 * NH * HD];
            vs[r][d] = qkv[base + (size_t)2 * NH * HD];
        }
        __syncthreads();

        float dot = 0.f;
#pragma unroll
        for (int d = 0; d < HD; d += 4) {
            float4 qv4 = *(const float4*)&qs[qi_s][d];
            float4 kv4 = *(const float4*)&ks[ki_s][d];
            dot += qv4.x * kv4.x + qv4.y * kv4.y + qv4.z * kv4.z + qv4.w * kv4.w;
        }
        float s = dot * 0.125f;

        float bm = s;
#pragma unroll
        for (int o = 8; o; o >>= 1) bm = fmaxf(bm, __shfl_xor_sync(0xffffffffu, bm, o, 16));
        float m_old = sm_m[qi_s];
        float m_new = fmaxf(m_old, bm);
        float p = __expf(s - m_new);
        float ps = p;
#pragma unroll
        for (int o = 8; o; o >>= 1) ps += __shfl_xor_sync(0xffffffffu, ps, o, 16);
        sP[qi_s][ki_s] = p;
        if (ki_s == 0) {
            float corr = __expf(m_old - m_new);
            sm_c[qi_s] = corr;
            sm_l[qi_s] = sm_l[qi_s] * corr + ps;
            sm_m[qi_s] = m_new;
        }
        __syncthreads();

#pragma unroll
        for (int ii = 0; ii < 4; ii++) {
            int qi = qg * 4 + ii;
            float sum = 0.f;
#pragma unroll
            for (int ki = 0; ki < BLK; ki++) sum += sP[qi][ki] * vs[ki][d_p];
            accv[ii] = accv[ii] * sm_c[qi] + sum;
        }
        __syncthreads();
    }

#pragma unroll
    for (int ii = 0; ii < 4; ii++) {
        int qi = qg * 4 + ii;
        float inv = 1.f / sm_l[qi];
        out[((size_t)bb * SS + q0 + qi) * DIM + hh * HD + d_p] = accv[ii] * inv;
    }
}

// ---------------- launch ----------------
extern "C" void kernel_launch(void* const* d_in, const int* in_sizes, int n_in,
                              void* d_out, int out_size) {
    const float* x        = (const float*)d_in[0];
    const float* c        = (const float*)d_in[1];
    const float* cosb     = (const float*)d_in[2];
    const float* sinb     = (const float*)d_in[3];
    /* d_in[4] = mask (recomputed analytically in-kernel) */
    const float* norm1_w  = (const float*)d_in[5];
    const float* qkv_w    = (const float*)d_in[6];
    const float* attn_w   = (const float*)d_in[7];
    const float* norm2_w  = (const float*)d_in[8];
    const float* mlp_w1   = (const float*)d_in[9];
    const float* mlp_b1   = (const float*)d_in[10];
    const float* mlp_w2   = (const float*)d_in[11];
    const float* mlp_b2   = (const float*)d_in[12];
    const float* adaLN_w  = (const float*)d_in[13];
    const float* adaLN_b  = (const float*)d_in[14];
    float* out = (float*)d_out;

    float *mods, *hbuf, *qkvb, *abuf, *x2, *mlp;
    cudaGetSymbolAddress((void**)&mods, g_mods);
    cudaGetSymbolAddress((void**)&hbuf, g_h);
    cudaGetSymbolAddress((void**)&qkvb, g_qkv);
    cudaGetSymbolAddress((void**)&abuf, g_a);
    cudaGetSymbolAddress((void**)&x2,   g_x2);
    cudaGetSymbolAddress((void**)&mlp,  g_mlp);

    // 1. adaLN modulation vector
    adaln_k<<<(BB * MODS + 255) / 256, 256>>>(c, adaLN_w, adaLN_b, mods);

    // 2. norm1 + modulate (shift_msa @0, scale_msa @DIM)
    ln_mod_k<<<MTOT, 256>>>(x, norm1_w, mods, hbuf, 0, DIM);

    // 3. QKV projection (tensor cores)
    gemm_tc_k<<<dim3(3 * DIM / 128, MTOT / 128), 128>>>(
        hbuf, qkv_w, qkvb, MTOT, 3 * DIM, DIM, nullptr, nullptr, nullptr, 0, 0);

    // 4. RoPE on whole qkv
    rope_k<<<(MTOT * 3 * NH * 32 + 255) / 256, 256>>>(qkvb, cosb, sinb);

    // 5. Block-sparse flash attention
    attn_blk_k<<<dim3(SS / BLK, BB * NH), 256>>>(qkvb, abuf);

    // 6. attn-out projection + gate_msa (@2*DIM) + x residual
    gemm_tc_k<<<dim3(DIM / 128, MTOT / 128), 128>>>(
        abuf, attn_w, x2, MTOT, DIM, DIM, nullptr, x, mods, 2 * DIM, 2);

    // 7. norm2 + modulate (shift_mlp @3*DIM, scale_mlp @4*DIM)
    ln_mod_k<<<MTOT, 256>>>(x2, norm2_w, mods, hbuf, 3 * DIM, 4 * DIM);

    // 8. MLP up + gelu
    gemm_tc_k<<<dim3(4 * DIM / 128, MTOT / 128), 128>>>(
        hbuf, mlp_w1, mlp, MTOT, 4 * DIM, DIM, mlp_b1, nullptr, nullptr, 0, 1);

    // 9. MLP down + bias + gate_mlp (@5*DIM) + x2 residual -> d_out
    gemm_tc_k<<<dim3(DIM / 128, MTOT / 128), 128>>>(
        mlp, mlp_w2, out, MTOT, DIM, 4 * DIM, mlp_b2, x2, mods, 5 * DIM, 2);
}

// round 5
// speedup vs baseline: 11.8382x; 1.5935x over previous
#include <cuda_runtime.h>
#include <math.h>
#include <stdint.h>

#define BB 2
#define NHALF 1024
#define SS 2048
#define DIM 768
#define NH 12
#define HD 64
#define COND 128
#define BLK 16
#define MTOT (BB*SS)          // 4096
#define MODS (6*DIM)          // 4608

// ---------------- scratch (device globals; no allocation allowed) ----------------
__device__ float g_mods[BB*MODS];
__device__ float g_h[MTOT*DIM];
__device__ float g_qkv[(size_t)MTOT*3*DIM];
__device__ float g_a[MTOT*DIM];
__device__ float g_x2[MTOT*DIM];
__device__ float g_mlp[(size_t)MTOT*4*DIM];

// ---------------- helpers ----------------
__device__ __forceinline__ float gelu_tanh(float x) {
    float x3 = x * x * x;
    return 0.5f * x * (1.f + tanhf(0.7978845608028654f * (x + 0.044715f * x3)));
}
__device__ __forceinline__ uint32_t f2tf32(float f) {
    uint32_t u;
    asm("cvt.rna.tf32.f32 %0, %1;" : "=r"(u) : "f"(f));
    return u;
}
__device__ __forceinline__ void mma_tf32(float c[4], const uint32_t a[4], const uint32_t b[2]) {
    asm volatile(
        "mma.sync.aligned.m16n8k8.row.col.f32.tf32.tf32.f32 "
        "{%0,%1,%2,%3},{%4,%5,%6,%7},{%8,%9},{%0,%1,%2,%3};"
        : "+f"(c[0]), "+f"(c[1]), "+f"(c[2]), "+f"(c[3])
        : "r"(a[0]), "r"(a[1]), "r"(a[2]), "r"(a[3]), "r"(b[0]), "r"(b[1]));
}

// ---------------- adaLN: mods = c @ W^T + b ----------------
__global__ void adaln_k(const float* __restrict__ c, const float* __restrict__ w,
                        const float* __restrict__ b, float* __restrict__ mods) {
    int j = blockIdx.x * blockDim.x + threadIdx.x;
    if (j >= BB * MODS) return;
    int bb = j / MODS;
    int n  = j % MODS;
    const float* cr = c + bb * COND;
    const float* wr = w + (size_t)n * COND;
    float acc = b[n];
#pragma unroll 8
    for (int k = 0; k < COND; k++) acc += cr[k] * wr[k];
    mods[j] = acc;
}

// ---------------- LayerNorm + modulate ----------------
__global__ void ln_mod_k(const float* __restrict__ x, const float* __restrict__ w,
                         const float* __restrict__ mods, float* __restrict__ out,
                         int shift_off, int scale_off) {
    int row = blockIdx.x;
    int bb  = row / SS;
    const float* xr = x + (size_t)row * DIM;
    int tid = threadIdx.x;

    float s = 0.f, s2 = 0.f;
    for (int j = tid; j < DIM; j += blockDim.x) {
        float v = xr[j];
        s += v; s2 += v * v;
    }
#pragma unroll
    for (int o = 16; o; o >>= 1) {
        s  += __shfl_xor_sync(0xffffffffu, s,  o);
        s2 += __shfl_xor_sync(0xffffffffu, s2, o);
    }
    __shared__ float wsum[8], wsum2[8];
    __shared__ float s_mu, s_rv;
    if ((tid & 31) == 0) { wsum[tid >> 5] = s; wsum2[tid >> 5] = s2; }
    __syncthreads();
    if (tid == 0) {
        float t = 0.f, t2 = 0.f;
        for (int i = 0; i < 8; i++) { t += wsum[i]; t2 += wsum2[i]; }
        float mu = t / DIM;
        float var = t2 / DIM - mu * mu;
        s_mu = mu;
        s_rv = rsqrtf(var + 1e-5f);
    }
    __syncthreads();
    float mu = s_mu, rv = s_rv;
    const float* msh = mods + bb * MODS + shift_off;
    const float* msc = mods + bb * MODS + scale_off;
    float* orow = out + (size_t)row * DIM;
    for (int j = tid; j < DIM; j += blockDim.x)
        orow[j] = (xr[j] - mu) * rv * w[j] * (1.f + msc[j]) + msh[j];
}

// ---------------- tf32 tensor-core GEMM ----------------
#define GSTR 36   // smem row stride (u32); 36 % 32 == 4 -> conflict-free frag gather

__global__ __launch_bounds__(128) void gemm_tc_k(
    const float* __restrict__ A, const float* __restrict__ Bw, float* __restrict__ C,
    int M, int Ncols, int K,
    const float* __restrict__ bias, const float* __restrict__ res,
    const float* __restrict__ mods, int gate_off, int mode) {
    __shared__ uint32_t As[128 * GSTR];   // [m][k] tf32 bits
    __shared__ uint32_t Bs[128 * GSTR];   // [n][k] tf32 bits
    int tid  = threadIdx.x;
    int wid  = tid >> 5, lane = tid & 31;
    int wm   = wid >> 1, wn = wid & 1;       // 2x2 warp grid
    int g    = lane >> 2, t = lane & 3;
    int m0   = blockIdx.y * 128, n0 = blockIdx.x * 128;

    float acc[4][8][4];
#pragma unroll
    for (int i = 0; i < 4; i++)
#pragma unroll
        for (int j = 0; j < 8; j++)
#pragma unroll
            for (int r = 0; r < 4; r++) acc[i][j][r] = 0.f;

    for (int k0 = 0; k0 < K; k0 += 32) {
#pragma unroll
        for (int i = 0; i < 8; i++) {
            int e = i * 128 + tid;
            int r = e >> 3, cc = (e & 7) * 4;
            float4 va = *(const float4*)&A [(size_t)(m0 + r) * K + k0 + cc];
            float4 vb = *(const float4*)&Bw[(size_t)(n0 + r) * K + k0 + cc];
            uint32_t* pa = &As[r * GSTR + cc];
            pa[0] = f2tf32(va.x); pa[1] = f2tf32(va.y);
            pa[2] = f2tf32(va.z); pa[3] = f2tf32(va.w);
            uint32_t* pb = &Bs[r * GSTR + cc];
            pb[0] = f2tf32(vb.x); pb[1] = f2tf32(vb.y);
            pb[2] = f2tf32(vb.z); pb[3] = f2tf32(vb.w);
        }
        __syncthreads();
#pragma unroll
        for (int ks = 0; ks < 4; ks++) {
            int kb = ks * 8;
            uint32_t af[4][4], bf[8][2];
#pragma unroll
            for (int mt = 0; mt < 4; mt++) {
                int r = wm * 64 + mt * 16 + g;
                af[mt][0] = As[r * GSTR + kb + t];
                af[mt][1] = As[(r + 8) * GSTR + kb + t];
                af[mt][2] = As[r * GSTR + kb + t + 4];
                af[mt][3] = As[(r + 8) * GSTR + kb + t + 4];
            }
#pragma unroll
            for (int nt = 0; nt < 8; nt++) {
                int rn = wn * 64 + nt * 8 + g;
                bf[nt][0] = Bs[rn * GSTR + kb + t];
                bf[nt][1] = Bs[rn * GSTR + kb + t + 4];
            }
#pragma unroll
            for (int mt = 0; mt < 4; mt++)
#pragma unroll
                for (int nt = 0; nt < 8; nt++) mma_tf32(acc[mt][nt], af[mt], bf[nt]);
        }
        __syncthreads();
    }

    // epilogue
#pragma unroll
    for (int mt = 0; mt < 4; mt++) {
        int r0 = m0 + wm * 64 + mt * 16 + g;
#pragma unroll
        for (int half = 0; half < 2; half++) {
            int m = r0 + half * 8;
            int bb = m / SS;
#pragma unroll
            for (int nt = 0; nt < 8; nt++) {
                int n = n0 + wn * 64 + nt * 8 + 2 * t;
                float v0 = acc[mt][nt][half * 2 + 0];
                float v1 = acc[mt][nt][half * 2 + 1];
                if (mode == 1) {
                    v0 = gelu_tanh(v0 + bias[n]);
                    v1 = gelu_tanh(v1 + bias[n + 1]);
                } else if (mode == 2) {
                    if (bias) { v0 += bias[n]; v1 += bias[n + 1]; }
                    float g0 = mods[bb * MODS + gate_off + n];
                    float g1 = mods[bb * MODS + gate_off + n + 1];
                    v0 = res[(size_t)m * Ncols + n]     + g0 * v0;
                    v1 = res[(size_t)m * Ncols + n + 1] + g1 * v1;
                }
                *(float2*)&C[(size_t)m * Ncols + n] = make_float2(v0, v1);
            }
        }
    }
}

// ---------------- RoPE over all of qkv ----------------
__global__ void rope_k(float* __restrict__ qkv, const float* __restrict__ cosb,
                       const float* __restrict__ sinb) {
    int i = blockIdx.x * blockDim.x + threadIdx.x;
    int total = MTOT * 3 * NH * (HD / 2);
    if (i >= total) return;
    int d = i & 31;
    int rest = i >> 5;
    int hh = rest % NH; rest /= NH;
    int t  = rest % 3;  rest /= 3;
    int s  = rest % SS;
    int bb = rest / SS;
    size_t base = ((((size_t)bb * SS + s) * 3 + t) * NH + hh) * HD;
    float x1 = qkv[base + d], x2 = qkv[base + d + 32];
    float c1 = cosb[s * HD + d],      sn1 = sinb[s * HD + d];
    float c2 = cosb[s * HD + d + 32], sn2 = sinb[s * HD + d + 32];
    qkv[base + d]      = x1 * c1 - x2 * sn1;
    qkv[base + d + 32] = x2 * c2 + x1 * sn2;
}

// ---------------- Block-sparse flash attention (tf32 MMA) ----------------
// One CTA per (blkq 0..63, b*h). 32 queries: rows 0-15 = half1 block blkq,
// rows 16-31 = half2 block blkq. Chunk 0 = the two own-blocks (32 keys,
// diagonal mask); chunks >=1 = contiguous half-2 prefix keys in 64-chunks.
#define QST 68
#define KST 68
#define PST 68
#define VST 72

__global__ __launch_bounds__(256) void attn_mma_k(const float* __restrict__ qkv,
                                                  float* __restrict__ out) {
    int blkq = 63 - blockIdx.x;          // heavy CTAs first
    int bh = blockIdx.y;
    int bb = bh / NH, hh = bh % NH;
    int q0a = blkq * BLK;
    int q0b = NHALF + blkq * BLK;

    __shared__ uint32_t Qs[32 * QST];
    __shared__ uint32_t Ks[64 * KST];    // P tile aliases rows 0-31 (after QK done)
    __shared__ uint32_t Vs[64 * VST];
    __shared__ float redmax[32][9];
    __shared__ float redsum[32][9];
    uint32_t* Ps = Ks;                   // alias: Ps written strictly after all QK reads

    int tid = threadIdx.x;
    int w = tid >> 5, lane = tid & 31;
    int g = lane >> 2, t = lane & 3;
    int sl = w * 8;                      // QK: key slice base; PV/out: d slice base

    // load Q (32 x 64) as tf32
    for (int e = tid; e < 32 * 16; e += 256) {
        int r = e >> 4, d4 = (e & 15) * 4;
        int qg = (r < 16) ? (q0a + r) : (q0b + r - 16);
        float4 v = *(const float4*)&qkv[((((size_t)bb * SS + qg) * 3 + 0) * NH + hh) * HD + d4];
        *(uint4*)&Qs[r * QST + d4] =
            make_uint4(f2tf32(v.x), f2tf32(v.y), f2tf32(v.z), f2tf32(v.w));
    }

    float m_st[4], l_st[4];
#pragma unroll
    for (int i = 0; i < 4; i++) { m_st[i] = -1e30f; l_st[i] = 0.f; }
    float co[2][4] = {};

    int nch = 1 + (blkq * BLK + 63) / 64;
    for (int ch = 0; ch < nch; ch++) {
        int len = (ch == 0) ? 32 : min(64, blkq * BLK - (ch - 1) * 64);
        __syncthreads();   // prev PV / Q-load complete before K/V overwrite
        for (int e = tid; e < len * 16; e += 256) {
            int r = e >> 4, d4 = (e & 15) * 4;
            int kg = (ch == 0) ? ((r < 16) ? (q0a + r) : (q0b + r - 16))
                               : (NHALF + (ch - 1) * 64 + r);
            size_t gb = (((size_t)bb * SS + kg) * 3) * NH * HD + (size_t)hh * HD + d4;
            float4 kv = *(const float4*)&qkv[gb + (size_t)NH * HD];
            float4 vv = *(const float4*)&qkv[gb + (size_t)2 * NH * HD];
            *(uint4*)&Ks[r * KST + d4] =
                make_uint4(f2tf32(kv.x), f2tf32(kv.y), f2tf32(kv.z), f2tf32(kv.w));
            *(uint4*)&Vs[r * VST + d4] =
                make_uint4(f2tf32(vv.x), f2tf32(vv.y), f2tf32(vv.z), f2tf32(vv.w));
        }
        if (len < 64) {   // zero V pad rows so P=0 x garbage never makes NaN
            for (int e = tid; e < (64 - len) * 16; e += 256) {
                int r = len + (e >> 4), d4 = (e & 15) * 4;
                *(uint4*)&Vs[r * VST + d4] = make_uint4(0, 0, 0, 0);
            }
        }
        __syncthreads();

        // ---- QK: scores 32x64, warp w owns keys [8w, 8w+8) ----
        float cqk[2][4] = {};
#pragma unroll
        for (int kd = 0; kd < 8; kd++) {
            int kb = kd * 8;
            uint32_t bf[2];
            bf[0] = Ks[(sl + g) * KST + kb + t];
            bf[1] = Ks[(sl + g) * KST + kb + t + 4];
#pragma unroll
            for (int mf = 0; mf < 2; mf++) {
                uint32_t af[4];
                int rm = mf * 16;
                af[0] = Qs[(rm + g) * QST + kb + t];
                af[1] = Qs[(rm + g + 8) * QST + kb + t];
                af[2] = Qs[(rm + g) * QST + kb + t + 4];
                af[3] = Qs[(rm + g + 8) * QST + kb + t + 4];
                mma_tf32(cqk[mf], af, bf);
            }
        }
        // mask + scale
        float sc[2][4];
#pragma unroll
        for (int mf = 0; mf < 2; mf++)
#pragma unroll
            for (int idx = 0; idx < 4; idx++) {
                int key = sl + 2 * t + (idx & 1);
                int row = mf * 16 + g + 8 * (idx >> 1);
                bool valid = (ch == 0) ? ((key < 32) && ((row < 16) == (key < 16)))
                                       : (key < len);
                sc[mf][idx] = valid ? cqk[mf][idx] * 0.125f : -1e30f;
            }
        // per-row warp max (rows i = mf*2+h -> row = (i>>1)*16 + (i&1)*8 + g)
        float rmax[4];
#pragma unroll
        for (int mf = 0; mf < 2; mf++)
#pragma unroll
            for (int h = 0; h < 2; h++)
                rmax[mf * 2 + h] = fmaxf(sc[mf][2 * h], sc[mf][2 * h + 1]);
#pragma unroll
        for (int i = 0; i < 4; i++) {
            rmax[i] = fmaxf(rmax[i], __shfl_xor_sync(0xffffffffu, rmax[i], 1));
            rmax[i] = fmaxf(rmax[i], __shfl_xor_sync(0xffffffffu, rmax[i], 2));
        }
        if (t == 0)
#pragma unroll
            for (int i = 0; i < 4; i++)
                redmax[(i >> 1) * 16 + (i & 1) * 8 + g][w] = rmax[i];
        __syncthreads();   // all QK reads of Ks done -> Ps alias safe below

        float mnew[4], corr[4];
#pragma unroll
        for (int i = 0; i < 4; i++) {
            int row = (i >> 1) * 16 + (i & 1) * 8 + g;
            float cm = -1e30f;
#pragma unroll
            for (int w2 = 0; w2 < 8; w2++) cm = fmaxf(cm, redmax[row][w2]);
            mnew[i] = fmaxf(m_st[i], cm);
            corr[i] = __expf(m_st[i] - mnew[i]);
            m_st[i] = mnew[i];
        }
        float psum[4] = {0.f, 0.f, 0.f, 0.f};
#pragma unroll
        for (int mf = 0; mf < 2; mf++)
#pragma unroll
            for (int idx = 0; idx < 4; idx++) {
                int i = mf * 2 + (idx >> 1);
                float p = __expf(sc[mf][idx] - mnew[i]);
                psum[i] += p;
                int key = sl + 2 * t + (idx & 1);
                int row = mf * 16 + g + 8 * (idx >> 1);
                Ps[row * PST + key] = f2tf32(p);
            }
#pragma unroll
        for (int i = 0; i < 4; i++) {
            psum[i] += __shfl_xor_sync(0xffffffffu, psum[i], 1);
            psum[i] += __shfl_xor_sync(0xffffffffu, psum[i], 2);
        }
        if (t == 0)
#pragma unroll
            for (int i = 0; i < 4; i++)
                redsum[(i >> 1) * 16 + (i & 1) * 8 + g][w] = psum[i];
        __syncthreads();   // Ps + sums visible

#pragma unroll
        for (int i = 0; i < 4; i++) {
            int row = (i >> 1) * 16 + (i & 1) * 8 + g;
            float tot = 0.f;
#pragma unroll
            for (int w2 = 0; w2 < 8; w2++) tot += redsum[row][w2];
            l_st[i] = l_st[i] * corr[i] + tot;
        }
        // rescale accumulators, then PV: warp w owns d slice [8w, 8w+8)
#pragma unroll
        for (int mf = 0; mf < 2; mf++)
#pragma unroll
            for (int idx = 0; idx < 4; idx++)
                co[mf][idx] *= corr[mf * 2 + (idx >> 1)];
#pragma unroll
        for (int kk = 0; kk < 8; kk++) {
            int kb = kk * 8;
            uint32_t bf[2];
            bf[0] = Vs[(kb + t) * VST + sl + g];
            bf[1] = Vs[(kb + t + 4) * VST + sl + g];
#pragma unroll
            for (int mf = 0; mf < 2; mf++) {
                uint32_t af[4];
                int rm = mf * 16;
                af[0] = Ps[(rm + g) * PST + kb + t];
                af[1] = Ps[(rm + g + 8) * PST + kb + t];
                af[2] = Ps[(rm + g) * PST + kb + t + 4];
                af[3] = Ps[(rm + g + 8) * PST + kb + t + 4];
                mma_tf32(co[mf], af, bf);
            }
        }
    }

    // output: row = mf*16 + 8h + g, col = hh*64 + sl + 2t + {0,1}
#pragma unroll
    for (int mf = 0; mf < 2; mf++)
#pragma unroll
        for (int h = 0; h < 2; h++) {
            int row = mf * 16 + 8 * h + g;
            int qg = (row < 16) ? (q0a + row) : (q0b + row - 16);
            float inv = 1.f / l_st[mf * 2 + h];
            *(float2*)&out[((size_t)bb * SS + qg) * DIM + hh * HD + sl + 2 * t] =
                make_float2(co[mf][2 * h] * inv, co[mf][2 * h + 1] * inv);
        }
}

// ---------------- launch ----------------
extern "C" void kernel_launch(void* const* d_in, const int* in_sizes, int n_in,
                              void* d_out, int out_size) {
    const float* x        = (const float*)d_in[0];
    const float* c        = (const float*)d_in[1];
    const float* cosb     = (const float*)d_in[2];
    const float* sinb     = (const float*)d_in[3];
    /* d_in[4] = mask (recomputed analytically in-kernel) */
    const float* norm1_w  = (const float*)d_in[5];
    const float* qkv_w    = (const float*)d_in[6];
    const float* attn_w   = (const float*)d_in[7];
    const float* norm2_w  = (const float*)d_in[8];
    const float* mlp_w1   = (const float*)d_in[9];
    const float* mlp_b1   = (const float*)d_in[10];
    const float* mlp_w2   = (const float*)d_in[11];
    const float* mlp_b2   = (const float*)d_in[12];
    const float* adaLN_w  = (const float*)d_in[13];
    const float* adaLN_b  = (const float*)d_in[14];
    float* out = (float*)d_out;

    float *mods, *hbuf, *qkvb, *abuf, *x2, *mlp;
    cudaGetSymbolAddress((void**)&mods, g_mods);
    cudaGetSymbolAddress((void**)&hbuf, g_h);
    cudaGetSymbolAddress((void**)&qkvb, g_qkv);
    cudaGetSymbolAddress((void**)&abuf, g_a);
    cudaGetSymbolAddress((void**)&x2,   g_x2);
    cudaGetSymbolAddress((void**)&mlp,  g_mlp);

    // 1. adaLN modulation vector
    adaln_k<<<(BB * MODS + 255) / 256, 256>>>(c, adaLN_w, adaLN_b, mods);

    // 2. norm1 + modulate (shift_msa @0, scale_msa @DIM)
    ln_mod_k<<<MTOT, 256>>>(x, norm1_w, mods, hbuf, 0, DIM);

    // 3. QKV projection (tensor cores)
    gemm_tc_k<<<dim3(3 * DIM / 128, MTOT / 128), 128>>>(
        hbuf, qkv_w, qkvb, MTOT, 3 * DIM, DIM, nullptr, nullptr, nullptr, 0, 0);

    // 4. RoPE on whole qkv
    rope_k<<<(MTOT * 3 * NH * 32 + 255) / 256, 256>>>(qkvb, cosb, sinb);

    // 5. Block-sparse flash attention (tf32 MMA, merged q-blocks)
    attn_mma_k<<<dim3(64, BB * NH), 256>>>(qkvb, abuf);

    // 6. attn-out projection + gate_msa (@2*DIM) + x residual
    gemm_tc_k<<<dim3(DIM / 128, MTOT / 128), 128>>>(
        abuf, attn_w, x2, MTOT, DIM, DIM, nullptr, x, mods, 2 * DIM, 2);

    // 7. norm2 + modulate (shift_mlp @3*DIM, scale_mlp @4*DIM)
    ln_mod_k<<<MTOT, 256>>>(x2, norm2_w, mods, hbuf, 3 * DIM, 4 * DIM);

    // 8. MLP up + gelu
    gemm_tc_k<<<dim3(4 * DIM / 128, MTOT / 128), 128>>>(
        hbuf, mlp_w1, mlp, MTOT, 4 * DIM, DIM, mlp_b1, nullptr, nullptr, 0, 1);

    // 9. MLP down + bias + gate_mlp (@5*DIM) + x2 residual -> d_out
    gemm_tc_k<<<dim3(DIM / 128, MTOT / 128), 128>>>(
        mlp, mlp_w2, out, MTOT, DIM, 4 * DIM, mlp_b2, x2, mods, 5 * DIM, 2);
}

// round 6
// speedup vs baseline: 15.1916x; 1.2833x over previous
#include <cuda_runtime.h>
#include <cuda_fp16.h>
#include <math.h>
#include <stdint.h>

#define BB 2
#define NHALF 1024
#define SS 2048
#define DIM 768
#define NH 12
#define HD 64
#define COND 128
#define BLK 16
#define MTOT (BB*SS)          // 4096
#define MODS (6*DIM)          // 4608

// weight arena offsets (halves)
#define W_QKV 0
#define W_ATT (W_QKV + 3*DIM*DIM)
#define W_M1  (W_ATT + DIM*DIM)
#define W_M2  (W_M1 + 4*DIM*DIM)
#define W_TOT (W_M2 + 4*DIM*DIM)

// ---------------- scratch (device globals; no allocation allowed) ----------------
__device__ float g_mods[BB*MODS];
__device__ __half g_h16[MTOT*DIM];
__device__ float g_qkv[(size_t)MTOT*3*DIM];
__device__ __half g_a16[MTOT*DIM];
__device__ float g_x2[MTOT*DIM];
__device__ __half g_mlp16[(size_t)MTOT*4*DIM];
__device__ __half g_w16[W_TOT];

// ---------------- helpers ----------------
__device__ __forceinline__ float gelu_tanh(float x) {
    float x3 = x * x * x;
    return 0.5f * x * (1.f + tanhf(0.7978845608028654f * (x + 0.044715f * x3)));
}
__device__ __forceinline__ uint32_t f2tf32(float f) {
    uint32_t u;
    asm("cvt.rna.tf32.f32 %0, %1;" : "=r"(u) : "f"(f));
    return u;
}
__device__ __forceinline__ void mma_tf32(float c[4], const uint32_t a[4], const uint32_t b[2]) {
    asm volatile(
        "mma.sync.aligned.m16n8k8.row.col.f32.tf32.tf32.f32 "
        "{%0,%1,%2,%3},{%4,%5,%6,%7},{%8,%9},{%0,%1,%2,%3};"
        : "+f"(c[0]), "+f"(c[1]), "+f"(c[2]), "+f"(c[3])
        : "r"(a[0]), "r"(a[1]), "r"(a[2]), "r"(a[3]), "r"(b[0]), "r"(b[1]));
}
__device__ __forceinline__ void mma_f16(float c[4], const uint32_t a[4], const uint32_t b[2]) {
    asm volatile(
        "mma.sync.aligned.m16n8k16.row.col.f32.f16.f16.f32 "
        "{%0,%1,%2,%3},{%4,%5,%6,%7},{%8,%9},{%0,%1,%2,%3};"
        : "+f"(c[0]), "+f"(c[1]), "+f"(c[2]), "+f"(c[3])
        : "r"(a[0]), "r"(a[1]), "r"(a[2]), "r"(a[3]), "r"(b[0]), "r"(b[1]));
}
__device__ __forceinline__ void cp16(uint32_t dst, const void* src) {
    asm volatile("cp.async.cg.shared.global [%0], [%1], 16;\n" :: "r"(dst), "l"(src));
}

// ---------------- weight fp32 -> fp16 conversion ----------------
__global__ void cvt_w_k(const float* __restrict__ w0, const float* __restrict__ w1,
                        const float* __restrict__ w2, const float* __restrict__ w3,
                        __half* __restrict__ dst) {
    int i4 = (blockIdx.x * 256 + threadIdx.x) * 4;
    if (i4 >= W_TOT) return;
    const float* src; int off;
    if (i4 < W_ATT)      { src = w0; off = i4 - W_QKV; }
    else if (i4 < W_M1)  { src = w1; off = i4 - W_ATT; }
    else if (i4 < W_M2)  { src = w2; off = i4 - W_M1; }
    else                 { src = w3; off = i4 - W_M2; }
    float4 v = *(const float4*)&src[off];
    *(half2*)&dst[i4]     = __floats2half2_rn(v.x, v.y);
    *(half2*)&dst[i4 + 2] = __floats2half2_rn(v.z, v.w);
}

// ---------------- adaLN: mods = c @ W^T + b ----------------
__global__ void adaln_k(const float* __restrict__ c, const float* __restrict__ w,
                        const float* __restrict__ b, float* __restrict__ mods) {
    int j = blockIdx.x * blockDim.x + threadIdx.x;
    if (j >= BB * MODS) return;
    int bb = j / MODS;
    int n  = j % MODS;
    const float* cr = c + bb * COND;
    const float* wr = w + (size_t)n * COND;
    float acc = b[n];
#pragma unroll 8
    for (int k = 0; k < COND; k++) acc += cr[k] * wr[k];
    mods[j] = acc;
}

// ---------------- LayerNorm + modulate -> fp16 ----------------
__global__ void ln_mod_k(const float* __restrict__ x, const float* __restrict__ w,
                         const float* __restrict__ mods, __half* __restrict__ out,
                         int shift_off, int scale_off) {
    int row = blockIdx.x;
    int bb  = row / SS;
    const float* xr = x + (size_t)row * DIM;
    int tid = threadIdx.x;

    float s = 0.f, s2 = 0.f;
    for (int j = tid; j < DIM; j += blockDim.x) {
        float v = xr[j];
        s += v; s2 += v * v;
    }
#pragma unroll
    for (int o = 16; o; o >>= 1) {
        s  += __shfl_xor_sync(0xffffffffu, s,  o);
        s2 += __shfl_xor_sync(0xffffffffu, s2, o);
    }
    __shared__ float wsum[8], wsum2[8];
    __shared__ float s_mu, s_rv;
    if ((tid & 31) == 0) { wsum[tid >> 5] = s; wsum2[tid >> 5] = s2; }
    __syncthreads();
    if (tid == 0) {
        float t = 0.f, t2 = 0.f;
        for (int i = 0; i < 8; i++) { t += wsum[i]; t2 += wsum2[i]; }
        float mu = t / DIM;
        float var = t2 / DIM - mu * mu;
        s_mu = mu;
        s_rv = rsqrtf(var + 1e-5f);
    }
    __syncthreads();
    float mu = s_mu, rv = s_rv;
    const float* msh = mods + bb * MODS + shift_off;
    const float* msc = mods + bb * MODS + scale_off;
    __half* orow = out + (size_t)row * DIM;
    for (int j = tid; j < DIM; j += blockDim.x)
        orow[j] = __float2half((xr[j] - mu) * rv * w[j] * (1.f + msc[j]) + msh[j]);
}

// ---------------- fp16 tensor-core GEMM, cp.async double-buffered ----------------
// C[M,N] = A[M,K] @ Bw[N,K]^T  (fp16 in, fp32 accum)
// mode 1: Ch = half(gelu(acc + bias[n]))
// mode 2: Cf = res + mods[gate]*(acc + bias?) (fp32)
// mode 3: Cf = rope(acc) (fp32, QKV layout: n -> (t3, head, d))
#define AST 40   // halves per smem row; 80B: frag u32 gather conflict-free

__global__ __launch_bounds__(128) void gemm_h_k(
    const __half* __restrict__ A, const __half* __restrict__ Bw,
    float* __restrict__ Cf, __half* __restrict__ Ch,
    int M, int Ncols, int K,
    const float* __restrict__ bias, const float* __restrict__ res,
    const float* __restrict__ mods, int gate_off, int mode,
    const float* __restrict__ cosb, const float* __restrict__ sinb) {
    __shared__ __half As[2][128 * AST];
    __shared__ __half Bs[2][128 * AST];
    int tid  = threadIdx.x;
    int wid  = tid >> 5, lane = tid & 31;
    int wm   = wid >> 1, wn = wid & 1;
    int g    = lane >> 2, t = lane & 3;
    int m0   = blockIdx.y * 128, n0 = blockIdx.x * 128;

    uint32_t aBase = (uint32_t)__cvta_generic_to_shared(&As[0][0]);
    uint32_t bBase = (uint32_t)__cvta_generic_to_shared(&Bs[0][0]);
    const int stageB = 128 * AST * 2;   // bytes per stage

    float acc[4][8][4];
#pragma unroll
    for (int i = 0; i < 4; i++)
#pragma unroll
        for (int j = 0; j < 8; j++)
#pragma unroll
            for (int r = 0; r < 4; r++) acc[i][j][r] = 0.f;

    int nIter = K >> 5;
    // prefetch of one 128x32 stage: 512 16B units per matrix, 4 per thread
    int pr = tid >> 2, pc = (tid & 3) * 8;           // fixed (row,col-chunk) role... 
    // (each thread does rows pr, pr+32, pr+64, pr+96 at col pc)
#define PREFETCH(it, s) {                                                           \
        int k0 = (it) << 5;                                                         \
        _Pragma("unroll")                                                           \
        for (int i = 0; i < 4; i++) {                                               \
            int r = pr + i * 32;                                                    \
            cp16(aBase + (s) * stageB + (r * AST + pc) * 2,                         \
                 A + (size_t)(m0 + r) * K + k0 + pc);                               \
            cp16(bBase + (s) * stageB + (r * AST + pc) * 2,                         \
                 Bw + (size_t)(n0 + r) * K + k0 + pc);                              \
        }                                                                           \
        asm volatile("cp.async.commit_group;\n");                                   \
    }

    PREFETCH(0, 0);
    int s = 0;
    for (int it = 0; it < nIter; it++) {
        if (it + 1 < nIter) {
            PREFETCH(it + 1, s ^ 1);
            asm volatile("cp.async.wait_group 1;\n");
        } else {
            asm volatile("cp.async.wait_group 0;\n");
        }
        __syncthreads();
        const __half* as = As[s];
        const __half* bs = Bs[s];
#pragma unroll
        for (int ks = 0; ks < 2; ks++) {
            int kb = ks * 16;
            uint32_t af[4][4], bf[8][2];
#pragma unroll
            for (int mt = 0; mt < 4; mt++) {
                int r = wm * 64 + mt * 16;
                af[mt][0] = *(const uint32_t*)&as[(r + g) * AST + kb + 2 * t];
                af[mt][1] = *(const uint32_t*)&as[(r + 8 + g) * AST + kb + 2 * t];
                af[mt][2] = *(const uint32_t*)&as[(r + g) * AST + kb + 2 * t + 8];
                af[mt][3] = *(const uint32_t*)&as[(r + 8 + g) * AST + kb + 2 * t + 8];
            }
#pragma unroll
            for (int nt = 0; nt < 8; nt++) {
                int rn = wn * 64 + nt * 8 + g;
                bf[nt][0] = *(const uint32_t*)&bs[rn * AST + kb + 2 * t];
                bf[nt][1] = *(const uint32_t*)&bs[rn * AST + kb + 2 * t + 8];
            }
#pragma unroll
            for (int mt = 0; mt < 4; mt++)
#pragma unroll
                for (int nt = 0; nt < 8; nt++) mma_f16(acc[mt][nt], af[mt], bf[nt]);
        }
        __syncthreads();
        s ^= 1;
    }

    // ---- epilogue ----
#pragma unroll
    for (int mt = 0; mt < 4; mt++) {
#pragma unroll
        for (int half_ = 0; half_ < 2; half_++) {
            int m = m0 + wm * 64 + mt * 16 + half_ * 8 + g;
            int bb = m / SS;
            if (mode == 3) {
                // QKV + RoPE: pairs (nt, nt+4) are (d, d+32) of one head
                int stok = m & (SS - 1);
#pragma unroll
                for (int nt = 0; nt < 4; nt++) {
                    int n = n0 + wn * 64 + nt * 8 + 2 * t;
                    int d = nt * 8 + 2 * t;
                    float y1[2], y2[2];
#pragma unroll
                    for (int j = 0; j < 2; j++) {
                        float x1 = acc[mt][nt][half_ * 2 + j];
                        float x2 = acc[mt][nt + 4][half_ * 2 + j];
                        float c1 = cosb[stok * HD + d + j];
                        float s1 = sinb[stok * HD + d + j];
                        float c2 = cosb[stok * HD + d + j + 32];
                        float s2 = sinb[stok * HD + d + j + 32];
                        y1[j] = x1 * c1 - x2 * s1;
                        y2[j] = x2 * c2 + x1 * s2;
                    }
                    *(float2*)&Cf[(size_t)m * Ncols + n]      = make_float2(y1[0], y1[1]);
                    *(float2*)&Cf[(size_t)m * Ncols + n + 32] = make_float2(y2[0], y2[1]);
                }
            } else {
#pragma unroll
                for (int nt = 0; nt < 8; nt++) {
                    int n = n0 + wn * 64 + nt * 8 + 2 * t;
                    float v0 = acc[mt][nt][half_ * 2 + 0];
                    float v1 = acc[mt][nt][half_ * 2 + 1];
                    if (mode == 1) {
                        v0 = gelu_tanh(v0 + bias[n]);
                        v1 = gelu_tanh(v1 + bias[n + 1]);
                        *(half2*)&Ch[(size_t)m * Ncols + n] = __floats2half2_rn(v0, v1);
                    } else {  // mode 2
                        if (bias) { v0 += bias[n]; v1 += bias[n + 1]; }
                        float g0 = mods[bb * MODS + gate_off + n];
                        float g1 = mods[bb * MODS + gate_off + n + 1];
                        v0 = res[(size_t)m * Ncols + n]     + g0 * v0;
                        v1 = res[(size_t)m * Ncols + n + 1] + g1 * v1;
                        *(float2*)&Cf[(size_t)m * Ncols + n] = make_float2(v0, v1);
                    }
                }
            }
        }
    }
}

// ---------------- Block-sparse flash attention (tf32 MMA) ----------------
#define QST 68
#define KST 68
#define PST 68
#define VST 72

__global__ __launch_bounds__(256) void attn_mma_k(const float* __restrict__ qkv,
                                                  __half* __restrict__ out) {
    int blkq = 63 - blockIdx.x;          // heavy CTAs first
    int bh = blockIdx.y;
    int bb = bh / NH, hh = bh % NH;
    int q0a = blkq * BLK;
    int q0b = NHALF + blkq * BLK;

    __shared__ uint32_t Qs[32 * QST];
    __shared__ uint32_t Ks[64 * KST];
    __shared__ uint32_t Vs[64 * VST];
    __shared__ float redmax[32][9];
    __shared__ float redsum[32][9];
    uint32_t* Ps = Ks;

    int tid = threadIdx.x;
    int w = tid >> 5, lane = tid & 31;
    int g = lane >> 2, t = lane & 3;
    int sl = w * 8;

    for (int e = tid; e < 32 * 16; e += 256) {
        int r = e >> 4, d4 = (e & 15) * 4;
        int qg = (r < 16) ? (q0a + r) : (q0b + r - 16);
        float4 v = *(const float4*)&qkv[((((size_t)bb * SS + qg) * 3 + 0) * NH + hh) * HD + d4];
        *(uint4*)&Qs[r * QST + d4] =
            make_uint4(f2tf32(v.x), f2tf32(v.y), f2tf32(v.z), f2tf32(v.w));
    }

    float m_st[4], l_st[4];
#pragma unroll
    for (int i = 0; i < 4; i++) { m_st[i] = -1e30f; l_st[i] = 0.f; }
    float co[2][4] = {};

    int nch = 1 + (blkq * BLK + 63) / 64;
    for (int ch = 0; ch < nch; ch++) {
        int len = (ch == 0) ? 32 : min(64, blkq * BLK - (ch - 1) * 64);
        __syncthreads();
        for (int e = tid; e < len * 16; e += 256) {
            int r = e >> 4, d4 = (e & 15) * 4;
            int kg = (ch == 0) ? ((r < 16) ? (q0a + r) : (q0b + r - 16))
                               : (NHALF + (ch - 1) * 64 + r);
            size_t gb = (((size_t)bb * SS + kg) * 3) * NH * HD + (size_t)hh * HD + d4;
            float4 kv = *(const float4*)&qkv[gb + (size_t)NH * HD];
            float4 vv = *(const float4*)&qkv[gb + (size_t)2 * NH * HD];
            *(uint4*)&Ks[r * KST + d4] =
                make_uint4(f2tf32(kv.x), f2tf32(kv.y), f2tf32(kv.z), f2tf32(kv.w));
            *(uint4*)&Vs[r * VST + d4] =
                make_uint4(f2tf32(vv.x), f2tf32(vv.y), f2tf32(vv.z), f2tf32(vv.w));
        }
        if (len < 64) {
            for (int e = tid; e < (64 - len) * 16; e += 256) {
                int r = len + (e >> 4), d4 = (e & 15) * 4;
                *(uint4*)&Vs[r * VST + d4] = make_uint4(0, 0, 0, 0);
            }
        }
        __syncthreads();

        float cqk[2][4] = {};
#pragma unroll
        for (int kd = 0; kd < 8; kd++) {
            int kb = kd * 8;
            uint32_t bf[2];
            bf[0] = Ks[(sl + g) * KST + kb + t];
            bf[1] = Ks[(sl + g) * KST + kb + t + 4];
#pragma unroll
            for (int mf = 0; mf < 2; mf++) {
                uint32_t af[4];
                int rm = mf * 16;
                af[0] = Qs[(rm + g) * QST + kb + t];
                af[1] = Qs[(rm + g + 8) * QST + kb + t];
                af[2] = Qs[(rm + g) * QST + kb + t + 4];
                af[3] = Qs[(rm + g + 8) * QST + kb + t + 4];
                mma_tf32(cqk[mf], af, bf);
            }
        }
        float sc[2][4];
#pragma unroll
        for (int mf = 0; mf < 2; mf++)
#pragma unroll
            for (int idx = 0; idx < 4; idx++) {
                int key = sl + 2 * t + (idx & 1);
                int row = mf * 16 + g + 8 * (idx >> 1);
                bool valid = (ch == 0) ? ((key < 32) && ((row < 16) == (key < 16)))
                                       : (key < len);
                sc[mf][idx] = valid ? cqk[mf][idx] * 0.125f : -1e30f;
            }
        float rmax[4];
#pragma unroll
        for (int mf = 0; mf < 2; mf++)
#pragma unroll
            for (int h = 0; h < 2; h++)
                rmax[mf * 2 + h] = fmaxf(sc[mf][2 * h], sc[mf][2 * h + 1]);
#pragma unroll
        for (int i = 0; i < 4; i++) {
            rmax[i] = fmaxf(rmax[i], __shfl_xor_sync(0xffffffffu, rmax[i], 1));
            rmax[i] = fmaxf(rmax[i], __shfl_xor_sync(0xffffffffu, rmax[i], 2));
        }
        if (t == 0)
#pragma unroll
            for (int i = 0; i < 4; i++)
                redmax[(i >> 1) * 16 + (i & 1) * 8 + g][w] = rmax[i];
        __syncthreads();

        float mnew[4], corr[4];
#pragma unroll
        for (int i = 0; i < 4; i++) {
            int row = (i >> 1) * 16 + (i & 1) * 8 + g;
            float cm = -1e30f;
#pragma unroll
            for (int w2 = 0; w2 < 8; w2++) cm = fmaxf(cm, redmax[row][w2]);
            mnew[i] = fmaxf(m_st[i], cm);
            corr[i] = __expf(m_st[i] - mnew[i]);
            m_st[i] = mnew[i];
        }
        float psum[4] = {0.f, 0.f, 0.f, 0.f};
#pragma unroll
        for (int mf = 0; mf < 2; mf++)
#pragma unroll
            for (int idx = 0; idx < 4; idx++) {
                int i = mf * 2 + (idx >> 1);
                float p = __expf(sc[mf][idx] - mnew[i]);
                psum[i] += p;
                int key = sl + 2 * t + (idx & 1);
                int row = mf * 16 + g + 8 * (idx >> 1);
                Ps[row * PST + key] = f2tf32(p);
            }
#pragma unroll
        for (int i = 0; i < 4; i++) {
            psum[i] += __shfl_xor_sync(0xffffffffu, psum[i], 1);
            psum[i] += __shfl_xor_sync(0xffffffffu, psum[i], 2);
        }
        if (t == 0)
#pragma unroll
            for (int i = 0; i < 4; i++)
                redsum[(i >> 1) * 16 + (i & 1) * 8 + g][w] = psum[i];
        __syncthreads();

#pragma unroll
        for (int i = 0; i < 4; i++) {
            int row = (i >> 1) * 16 + (i & 1) * 8 + g;
            float tot = 0.f;
#pragma unroll
            for (int w2 = 0; w2 < 8; w2++) tot += redsum[row][w2];
            l_st[i] = l_st[i] * corr[i] + tot;
        }
#pragma unroll
        for (int mf = 0; mf < 2; mf++)
#pragma unroll
            for (int idx = 0; idx < 4; idx++)
                co[mf][idx] *= corr[mf * 2 + (idx >> 1)];
#pragma unroll
        for (int kk = 0; kk < 8; kk++) {
            int kb = kk * 8;
            uint32_t bf[2];
            bf[0] = Vs[(kb + t) * VST + sl + g];
            bf[1] = Vs[(kb + t + 4) * VST + sl + g];
#pragma unroll
            for (int mf = 0; mf < 2; mf++) {
                uint32_t af[4];
                int rm = mf * 16;
                af[0] = Ps[(rm + g) * PST + kb + t];
                af[1] = Ps[(rm + g + 8) * PST + kb + t];
                af[2] = Ps[(rm + g) * PST + kb + t + 4];
                af[3] = Ps[(rm + g + 8) * PST + kb + t + 4];
                mma_tf32(co[mf], af, bf);
            }
        }
    }

#pragma unroll
    for (int mf = 0; mf < 2; mf++)
#pragma unroll
        for (int h = 0; h < 2; h++) {
            int row = mf * 16 + 8 * h + g;
            int qg = (row < 16) ? (q0a + row) : (q0b + row - 16);
            float inv = 1.f / l_st[mf * 2 + h];
            *(half2*)&out[((size_t)bb * SS + qg) * DIM + hh * HD + sl + 2 * t] =
                __floats2half2_rn(co[mf][2 * h] * inv, co[mf][2 * h + 1] * inv);
        }
}

// ---------------- launch ----------------
extern "C" void kernel_launch(void* const* d_in, const int* in_sizes, int n_in,
                              void* d_out, int out_size) {
    const float* x        = (const float*)d_in[0];
    const float* c        = (const float*)d_in[1];
    const float* cosb     = (const float*)d_in[2];
    const float* sinb     = (const float*)d_in[3];
    /* d_in[4] = mask (recomputed analytically in-kernel) */
    const float* norm1_w  = (const float*)d_in[5];
    const float* qkv_w    = (const float*)d_in[6];
    const float* attn_w   = (const float*)d_in[7];
    const float* norm2_w  = (const float*)d_in[8];
    const float* mlp_w1   = (const float*)d_in[9];
    const float* mlp_b1   = (const float*)d_in[10];
    const float* mlp_w2   = (const float*)d_in[11];
    const float* mlp_b2   = (const float*)d_in[12];
    const float* adaLN_w  = (const float*)d_in[13];
    const float* adaLN_b  = (const float*)d_in[14];
    float* out = (float*)d_out;

    float *mods, *qkvb, *x2;
    __half *h16, *a16, *mlp16, *w16;
    cudaGetSymbolAddress((void**)&mods,  g_mods);
    cudaGetSymbolAddress((void**)&h16,   g_h16);
    cudaGetSymbolAddress((void**)&qkvb,  g_qkv);
    cudaGetSymbolAddress((void**)&a16,   g_a16);
    cudaGetSymbolAddress((void**)&x2,    g_x2);
    cudaGetSymbolAddress((void**)&mlp16, g_mlp16);
    cudaGetSymbolAddress((void**)&w16,   g_w16);

    // 0. convert weights to fp16 arena
    cvt_w_k<<<(W_TOT / 4 + 255) / 256, 256>>>(qkv_w, attn_w, mlp_w1, mlp_w2, w16);

    // 1. adaLN modulation vector
    adaln_k<<<(BB * MODS + 255) / 256, 256>>>(c, adaLN_w, adaLN_b, mods);

    // 2. norm1 + modulate (shift_msa @0, scale_msa @DIM) -> fp16
    ln_mod_k<<<MTOT, 256>>>(x, norm1_w, mods, h16, 0, DIM);

    // 3. QKV projection + fused RoPE (mode 3) -> fp32 qkv
    gemm_h_k<<<dim3(3 * DIM / 128, MTOT / 128), 128>>>(
        h16, w16 + W_QKV, qkvb, nullptr, MTOT, 3 * DIM, DIM,
        nullptr, nullptr, nullptr, 0, 3, cosb, sinb);

    // 4. Block-sparse flash attention (tf32 MMA) -> fp16 a
    attn_mma_k<<<dim3(64, BB * NH), 256>>>(qkvb, a16);

    // 5. attn-out projection + gate_msa (@2*DIM) + x residual -> fp32 x2
    gemm_h_k<<<dim3(DIM / 128, MTOT / 128), 128>>>(
        a16, w16 + W_ATT, x2, nullptr, MTOT, DIM, DIM,
        nullptr, x, mods, 2 * DIM, 2, nullptr, nullptr);

    // 6. norm2 + modulate (shift_mlp @3*DIM, scale_mlp @4*DIM) -> fp16
    ln_mod_k<<<MTOT, 256>>>(x2, norm2_w, mods, h16, 3 * DIM, 4 * DIM);

    // 7. MLP up + gelu (mode 1) -> fp16 mlp
    gemm_h_k<<<dim3(4 * DIM / 128, MTOT / 128), 128>>>(
        h16, w16 + W_M1, nullptr, mlp16, MTOT, 4 * DIM, DIM,
        mlp_b1, nullptr, nullptr, 0, 1, nullptr, nullptr);

    // 8. MLP down + bias + gate_mlp (@5*DIM) + x2 residual -> d_out
    gemm_h_k<<<dim3(DIM / 128, MTOT / 128), 128>>>(
        mlp16, w16 + W_M2, out, nullptr, MTOT, DIM, 4 * DIM,
        mlp_b2, x2, mods, 5 * DIM, 2, nullptr, nullptr);
}